// round 16
// baseline (speedup 1.0000x reference)
#include <cuda_runtime.h>
#include <stdint.h>

#define WIMG 4001
#define HW   ((size_t)4001 * (size_t)4001)
#define P0   4008
#define NT   493
#define NTILES (NT * NT)
#define CAP  4096

// ---------------- scratch ----------------
__device__ float g_EG[2][4001][P0];     // gray / gray^2, padded cols 0..4002
__device__ float g_SG[2][4001][P0];     // axis-0 scanned
__device__ float g_II[2][4001][P0];     // integral images
__device__ float g_TS[4100][8032];      // per-line scan workspace, [pos][slot]
__device__ unsigned g_stds[NTILES];
__device__ unsigned g_hist[65536];
__device__ unsigned g_hist2[65536];
__device__ unsigned g_misc[4];
__device__ unsigned long long g_cand[CAP];
__device__ int g_sel[64];

// ---------------------------------------------------------------------------
// Gray: XLA-CPU einsum with LLVM FMA contraction, ascending:
//   acc = w0*t0; acc = fma(w1,t1,acc); acc = fma(w2,t2,acc)
// ---------------------------------------------------------------------------
__global__ __launch_bounds__(256) void kGray(const float* __restrict__ in) {
    long idx = (long)blockIdx.x * 256 + threadIdx.x;
    if (idx >= (long)4001 * 4003) return;
    int r = (int)(idx / 4003), cp = (int)(idx % 4003);
    float g = 0.0f;
    if (cp >= 1 && cp <= 4001) {
        size_t o = (size_t)r * WIMG + (cp - 1);
        float t0 = in[o], t1 = in[o + HW], t2 = in[o + 2 * HW];
        g = __fmaf_rn(0.114f, t2, __fmaf_rn(0.587f, t1, __fmul_rn(0.2989f, t0)));
    }
    g_EG[0][r][cp] = g;
    g_EG[1][r][cp] = __fmul_rn(g, g);
}

// ---------------------------------------------------------------------------
// XLA ReduceWindowRewriter scan, base B = 16, full recursion:
//   per-16-block ascending scans; block totals -> recurse; add-back offsets.
// ---------------------------------------------------------------------------
__device__ void scan_rw16(int tid, int n) {
    const int B = 16;
    int n1 = (n + B - 1) / B;       // 251 for both axes
    float t1[256];
    for (int b = 0; b < n1; b++) {
        float acc = 0.0f;
        int e = min(n, (b + 1) * B);
        for (int j = b * B; j < e; j++) {
            acc = __fadd_rn(acc, g_TS[j][tid]);
            g_TS[j][tid] = acc;
        }
        t1[b] = acc;
    }
    // n1 = 251 > 16 -> recurse one level (n2 = 16 <= 16 -> naive)
    int n2 = (n1 + B - 1) / B;
    float t2[16];
    for (int b = 0; b < n2; b++) {
        float acc = 0.0f;
        int e = min(n1, (b + 1) * B);
        for (int j = b * B; j < e; j++) {
            acc = __fadd_rn(acc, t1[j]);
            t1[j] = acc;
        }
        t2[b] = acc;
    }
    for (int k = 1; k < n2; k++) t2[k] = __fadd_rn(t2[k - 1], t2[k]);
    for (int i = B; i < n1; i++)
        t1[i] = __fadd_rn(t2[i / B - 1], t1[i]);
    for (int i = B; i < n; i++)
        g_TS[i][tid] = __fadd_rn(t1[i / B - 1], g_TS[i][tid]);
}

__global__ __launch_bounds__(256) void kScan0() {
    int tid = blockIdx.x * 256 + threadIdx.x;
    if (tid >= 2 * 4003) return;
    int a = tid / 4003, col = tid % 4003;
    for (int r = 0; r < 4001; r++) g_TS[r][tid] = g_EG[a][r][col];
    scan_rw16(tid, 4001);
    for (int r = 0; r < 4001; r++) g_SG[a][r][col] = g_TS[r][tid];
}

__global__ __launch_bounds__(256) void kScan1() {
    int tid = blockIdx.x * 256 + threadIdx.x;
    if (tid >= 2 * 4001) return;
    int a = tid / 4001, row = tid % 4001;
    for (int c = 0; c < 4003; c++) g_TS[c][tid] = g_SG[a][row][c];
    scan_rw16(tid, 4003);
    for (int c = 0; c < 4003; c++) g_II[a][row][c] = g_TS[c][tid];
}

// ---------------------------------------------------------------------------
// Per-tile std (faithful op order)
// ---------------------------------------------------------------------------
__global__ __launch_bounds__(256) void kStd(unsigned* __restrict__ out) {
    int t = blockIdx.x * 256 + threadIdx.x;
    if (t >= NTILES) return;
    int ti = t / NT, tj = t % NT;
    size_t r0 = (size_t)(8 * ti) * P0, r1 = (size_t)(8 * ti + 64) * P0;
    int c0 = 8 * tj, c1 = 8 * tj + 64;
    const float* I1 = &g_II[0][0][0];
    const float* I2 = &g_II[1][0][0];
    float s1 = __fsub_rn(__fsub_rn(__fadd_rn(I1[r1 + c1], I1[r0 + c0]), I1[r0 + c1]), I1[r1 + c0]);
    float s2 = __fsub_rn(__fsub_rn(__fadd_rn(I2[r1 + c1], I2[r0 + c0]), I2[r0 + c1]), I2[r1 + c0]);
    float v  = __fdiv_rn(__fsub_rn(s2, __fdiv_rn(__fmul_rn(s1, s1), 4096.0f)), 4096.0f);
    out[t] = __float_as_uint(__fsqrt_rn(v));
}

// ---------------------------------------------------------------------------
// Selection (two-level histogram -> candidates -> exact stable rank)
// ---------------------------------------------------------------------------
__global__ void k3h(const unsigned* __restrict__ stds) {
    int t = blockIdx.x * blockDim.x + threadIdx.x;
    if (t >= NTILES) return;
    atomicAdd(&g_hist[stds[t] >> 16], 1u);
}
__global__ __launch_bounds__(256) void k4a() {
    __shared__ unsigned part[256];
    unsigned s = 0;
    for (int i = 0; i < 256; i++) s += g_hist[threadIdx.x * 256 + i];
    part[threadIdx.x] = s;
    __syncthreads();
    if (threadIdx.x == 0) {
        unsigned cum = 0; int seg = 0;
        for (; seg < 256; seg++) { if (cum + part[seg] >= 64) break; cum += part[seg]; }
        unsigned B = 65535u;
        if (seg < 256)
            for (int i = seg * 256; i < seg * 256 + 256; i++) {
                if (cum + g_hist[i] >= 64) { B = (unsigned)i; break; }
                cum += g_hist[i];
            }
        g_misc[1] = B; g_misc[2] = cum;
    }
}
__global__ void k3b(const unsigned* __restrict__ stds) {
    int t = blockIdx.x * blockDim.x + threadIdx.x;
    if (t >= NTILES) return;
    unsigned b = stds[t];
    if ((b >> 16) == g_misc[1]) atomicAdd(&g_hist2[b & 0xffffu], 1u);
}
__global__ __launch_bounds__(256) void k4b() {
    __shared__ unsigned part[256];
    unsigned s = 0;
    for (int i = 0; i < 256; i++) s += g_hist2[threadIdx.x * 256 + i];
    part[threadIdx.x] = s;
    __syncthreads();
    if (threadIdx.x == 0) {
        unsigned cum = g_misc[2]; int seg = 0;
        for (; seg < 256; seg++) { if (cum + part[seg] >= 64) break; cum += part[seg]; }
        unsigned S = 65535u;
        if (seg < 256)
            for (int i = seg * 256; i < seg * 256 + 256; i++) {
                if (cum + g_hist2[i] >= 64) { S = (unsigned)i; break; }
                cum += g_hist2[i];
            }
        g_misc[3] = S;
    }
}
__global__ void k5(const unsigned* __restrict__ stds) {
    int t = blockIdx.x * blockDim.x + threadIdx.x;
    if (t >= NTILES) return;
    unsigned b = stds[t];
    unsigned top = b >> 16, B = g_misc[1], S = g_misc[3];
    if (top < B || (top == B && (b & 0xffffu) <= S)) {
        unsigned pos = atomicAdd(&g_misc[0], 1u);
        if (pos < CAP) g_cand[pos] = ((unsigned long long)b << 32) | (unsigned)t;
    }
}
__global__ __launch_bounds__(256) void k6(int* __restrict__ sel) {
    __shared__ unsigned long long c[CAP];
    unsigned cnt = g_misc[0];
    int n = (cnt < CAP) ? (int)cnt : CAP;
    for (int i = threadIdx.x; i < n; i += 256) c[i] = g_cand[i];
    __syncthreads();
    for (int i = threadIdx.x; i < n; i += 256) {
        unsigned long long ki = c[i];
        int rank = 0;
        for (int jj = 0; jj < n; jj++) rank += (c[jj] < ki);
        if (rank < 64) sel[rank] = (int)(ki & 0xffffffffu);
    }
}

// ---------------------------------------------------------------------------
// Fold: all 64 slots from the single (base-16, fma-asc) ranking
// ---------------------------------------------------------------------------
__global__ __launch_bounds__(256) void k7(const float* __restrict__ in, float* __restrict__ out) {
    int k = blockIdx.x, ch = blockIdx.y;
    int t = g_sel[k];
    int h = (t / NT) * 8, w = (t % NT) * 8;
    const float* src = in + (size_t)ch * HW + (size_t)h * WIMG + w;
    float* dst = out + (size_t)ch * (512 * 512) + (size_t)(k >> 3) * 64 * 512 + (k & 7) * 64;
    for (int e = threadIdx.x; e < 4096; e += 256) {
        int r = e >> 6, cc = e & 63;
        dst[(size_t)r * 512 + cc] = src[(size_t)r * WIMG + cc];
    }
}

// ---------------------------------------------------------------------------
extern "C" void kernel_launch(void* const* d_in, const int* in_sizes, int n_in,
                              void* d_out, int out_size) {
    const float* in = (const float*)d_in[0];
    float* out = (float*)d_out;

    unsigned *stds, *hist, *hist2, *misc;
    int* sel;
    cudaGetSymbolAddress((void**)&stds, g_stds);
    cudaGetSymbolAddress((void**)&hist, g_hist);
    cudaGetSymbolAddress((void**)&hist2, g_hist2);
    cudaGetSymbolAddress((void**)&misc, g_misc);
    cudaGetSymbolAddress((void**)&sel, g_sel);

    auto blocks = [](long n) { return (unsigned)((n + 255) / 256); };

    cudaMemsetAsync(hist, 0, 65536 * sizeof(unsigned));
    cudaMemsetAsync(hist2, 0, 65536 * sizeof(unsigned));
    cudaMemsetAsync(misc, 0, 4 * sizeof(unsigned));

    kGray<<<blocks((long)4001 * 4003), 256>>>(in);
    kScan0<<<blocks(2L * 4003), 256>>>();
    kScan1<<<blocks(2L * 4001), 256>>>();
    kStd<<<blocks(NTILES), 256>>>(stds);

    k3h<<<blocks(NTILES), 256>>>(stds);
    k4a<<<1, 256>>>();
    k3b<<<blocks(NTILES), 256>>>(stds);
    k4b<<<1, 256>>>();
    k5<<<blocks(NTILES), 256>>>(stds);
    k6<<<1, 256>>>(sel);

    k7<<<dim3(64, 3), 256>>>(in, out);
}

// round 17
// speedup vs baseline: 29.7080x; 29.7080x over previous
#include <cuda_runtime.h>
#include <stdint.h>

#define WIMG 4001
#define HW   ((size_t)4001 * (size_t)4001)
#define NC   4001
#define NB   251              // ceil(4001/16) == ceil(4003/16)
#define NR   501              // needed rows/cols on 8-lattice
#define NT   493
#define NTILES (NT * NT)
#define CAP  4096

// ---------------- scratch ----------------
__device__ float g_T1[2][NB][NC];    // axis-0 block totals -> scanned in place
__device__ float g_I9[2][NB][NC];    // axis-0 9-element ascending prefixes
__device__ float g_X0[2][NB][NC];    // axis-0 block first elements
__device__ float g_TT[2][16][NC];    // axis-0 level-2 totals -> scanned in place
__device__ float g_SGn[2][NR][NC];   // axis-0 scan at needed rows (all cols)
__device__ float g_T1c[2][NR][NB];   // axis-1 block totals -> scanned in place
__device__ float g_I9c[2][NR][NB];
__device__ float g_X0c[2][NR][NB];
__device__ float g_TTc[2][NR][16];
__device__ float g_IId[2][NR][504];  // downsampled integral images
__device__ unsigned g_stds[NTILES];
__device__ unsigned g_hist[65536];
__device__ unsigned g_hist2[65536];
__device__ unsigned g_misc[4];
__device__ unsigned long long g_cand[CAP];
__device__ int g_sel[64];

// ---------------------------------------------------------------------------
// K1: fused gray + axis-0 per-16-block ascending sums (input read exactly once)
// gray = fma(0.114,t2, fma(0.587,t1, 0.2989*t0))   [the verified recipe]
// ---------------------------------------------------------------------------
__global__ __launch_bounds__(256) void K1(const float* __restrict__ in) {
    int col = blockIdx.x * 256 + threadIdx.x;
    if (col >= NC) return;
    int b = blockIdx.y;
    int r0 = 16 * b, e = min(4001, r0 + 16);
    float as = 0.0f, aq = 0.0f;
    float x0s = 0.0f, x0q = 0.0f, i9s = 0.0f, i9q = 0.0f;
    for (int r = r0; r < e; r++) {
        size_t o = (size_t)r * WIMG + col;
        float t0 = in[o], t1 = in[o + HW], t2 = in[o + 2 * HW];
        float g = __fmaf_rn(0.114f, t2, __fmaf_rn(0.587f, t1, __fmul_rn(0.2989f, t0)));
        float q = __fmul_rn(g, g);
        as = __fadd_rn(as, g);
        aq = __fadd_rn(aq, q);
        if (r == r0)     { x0s = g;  x0q = q;  }
        if (r == r0 + 8) { i9s = as; i9q = aq; }
    }
    g_T1[0][b][col] = as;  g_T1[1][b][col] = aq;
    g_I9[0][b][col] = i9s; g_I9[1][b][col] = i9q;
    g_X0[0][b][col] = x0s; g_X0[1][b][col] = x0q;
}

// ---------------------------------------------------------------------------
// K2a/b/c: two-level (base-16) scan of the 251 axis-0 block totals, per column
// — exact scan_rw16 recursion, split for parallelism
// ---------------------------------------------------------------------------
__global__ __launch_bounds__(256) void K2a() {     // inner-16 scans of T1 + totals
    int idx = blockIdx.x * 256 + threadIdx.x;      // a*16*NC + m*NC + col
    if (idx >= 2 * 16 * NC) return;
    int a = idx / (16 * NC), rem = idx % (16 * NC);
    int m = rem / NC, col = rem % NC;
    int i0 = 16 * m, e = min(NB, i0 + 16);
    float acc = 0.0f;
    for (int i = i0; i < e; i++) {
        acc = __fadd_rn(acc, g_T1[a][i][col]);
        g_T1[a][i][col] = acc;
    }
    g_TT[a][m][col] = acc;
}
__global__ __launch_bounds__(256) void K2b() {     // naive scan of the 16 level-2 totals
    int idx = blockIdx.x * 256 + threadIdx.x;
    if (idx >= 2 * NC) return;
    int a = idx / NC, col = idx % NC;
    float acc = g_TT[a][0][col];
    for (int k = 1; k < 16; k++) {
        acc = __fadd_rn(acc, g_TT[a][k][col]);
        g_TT[a][k][col] = acc;
    }
}
__global__ __launch_bounds__(256) void K2c() {     // add level-2 offsets back
    int idx = blockIdx.x * 256 + threadIdx.x;      // a*(NB-16)*NC + (i-16)*NC + col
    if (idx >= 2 * (NB - 16) * NC) return;
    int a = idx / ((NB - 16) * NC), rem = idx % ((NB - 16) * NC);
    int i = 16 + rem / NC, col = rem % NC;
    g_T1[a][i][col] = __fadd_rn(g_TT[a][i / 16 - 1][col], g_T1[a][i][col]);
}

// ---------------------------------------------------------------------------
// K3: axis-0 scan values at needed rows r = 8k:  val = t1s[b-1] + inner
// ---------------------------------------------------------------------------
__global__ __launch_bounds__(256) void K3() {
    long idx = (long)blockIdx.x * 256 + threadIdx.x;    // a*NR*NC + k*NC + col
    if (idx >= 2L * NR * NC) return;
    int a = (int)(idx / ((long)NR * NC));
    long rem = idx % ((long)NR * NC);
    int k = (int)(rem / NC), col = (int)(rem % NC);
    int b = k >> 1;
    float inner = (k & 1) ? g_I9[a][b][col] : g_X0[a][b][col];
    float v = b ? __fadd_rn(g_T1[a][b - 1][col], inner) : inner;
    g_SGn[a][k][col] = v;
}

// ---------------------------------------------------------------------------
// K4: axis-1 per-16-block ascending sums over padded cols (p=0 and p=4002 are 0)
// ---------------------------------------------------------------------------
__global__ __launch_bounds__(256) void K4() {
    int idx = blockIdx.x * 256 + threadIdx.x;       // a*NR*NB + r8*NB + b
    if (idx >= 2 * NR * NB) return;
    int a = idx / (NR * NB), rem = idx % (NR * NB);
    int r8 = rem / NB, b = rem % NB;
    int p0 = 16 * b, e = min(4003, p0 + 16);
    float acc = 0.0f, x0 = 0.0f, i9 = 0.0f;
    for (int p = p0; p < e; p++) {
        float v = (p >= 1 && p <= 4001) ? g_SGn[a][r8][p - 1] : 0.0f;
        acc = __fadd_rn(acc, v);
        if (p == p0)     x0 = v;
        if (p == p0 + 8) i9 = acc;
    }
    g_T1c[a][r8][b] = acc;
    g_I9c[a][r8][b] = i9;
    g_X0c[a][r8][b] = x0;
}

// K5a/b/c: two-level scan of the 251 axis-1 block totals, per row
__global__ __launch_bounds__(256) void K5a() {
    int idx = blockIdx.x * 256 + threadIdx.x;       // a*NR*16 + r8*16 + m
    if (idx >= 2 * NR * 16) return;
    int a = idx / (NR * 16), rem = idx % (NR * 16);
    int r8 = rem / 16, m = rem % 16;
    int i0 = 16 * m, e = min(NB, i0 + 16);
    float acc = 0.0f;
    for (int i = i0; i < e; i++) {
        acc = __fadd_rn(acc, g_T1c[a][r8][i]);
        g_T1c[a][r8][i] = acc;
    }
    g_TTc[a][r8][m] = acc;
}
__global__ __launch_bounds__(256) void K5b() {
    int idx = blockIdx.x * 256 + threadIdx.x;
    if (idx >= 2 * NR) return;
    int a = idx / NR, r8 = idx % NR;
    float acc = g_TTc[a][r8][0];
    for (int k = 1; k < 16; k++) {
        acc = __fadd_rn(acc, g_TTc[a][r8][k]);
        g_TTc[a][r8][k] = acc;
    }
}
__global__ __launch_bounds__(256) void K5c() {
    int idx = blockIdx.x * 256 + threadIdx.x;       // a*NR*(NB-16) + r8*(NB-16) + (i-16)
    if (idx >= 2 * NR * (NB - 16)) return;
    int a = idx / (NR * (NB - 16)), rem = idx % (NR * (NB - 16));
    int r8 = rem / (NB - 16), i = 16 + rem % (NB - 16);
    g_T1c[a][r8][i] = __fadd_rn(g_TTc[a][r8][i / 16 - 1], g_T1c[a][r8][i]);
}

// K6: emit downsampled integral image at padded cols p = 8k
__global__ __launch_bounds__(256) void K6() {
    int idx = blockIdx.x * 256 + threadIdx.x;       // a*NR*NR + r8*NR + k
    if (idx >= 2 * NR * NR) return;
    int a = idx / (NR * NR), rem = idx % (NR * NR);
    int r8 = rem / NR, k = rem % NR;
    float v;
    if (k == 0) v = 0.0f;
    else {
        int m = k >> 1;
        float inner = (k & 1) ? g_I9c[a][r8][m] : g_X0c[a][r8][m];
        v = m ? __fadd_rn(g_T1c[a][r8][m - 1], inner) : inner;
    }
    g_IId[a][r8][k] = v;
}

// ---------------------------------------------------------------------------
// Per-tile std (faithful op order) on the downsampled lattice
// ---------------------------------------------------------------------------
__global__ __launch_bounds__(256) void kStd(unsigned* __restrict__ out) {
    int t = blockIdx.x * 256 + threadIdx.x;
    if (t >= NTILES) return;
    int ti = t / NT, tj = t % NT;
    int o = ti * 504 + tj;
    const float* I1 = &g_IId[0][0][0];
    const float* I2 = &g_IId[1][0][0];
    float s1 = __fsub_rn(__fsub_rn(__fadd_rn(I1[o + 8 * 504 + 8], I1[o]), I1[o + 8]), I1[o + 8 * 504]);
    float s2 = __fsub_rn(__fsub_rn(__fadd_rn(I2[o + 8 * 504 + 8], I2[o]), I2[o + 8]), I2[o + 8 * 504]);
    float v  = __fdiv_rn(__fsub_rn(s2, __fdiv_rn(__fmul_rn(s1, s1), 4096.0f)), 4096.0f);
    out[t] = __float_as_uint(__fsqrt_rn(v));
}

// ---------------------------------------------------------------------------
// Selection (two-level histogram -> candidates -> exact stable rank)
// ---------------------------------------------------------------------------
__global__ void k3h(const unsigned* __restrict__ stds) {
    int t = blockIdx.x * blockDim.x + threadIdx.x;
    if (t >= NTILES) return;
    atomicAdd(&g_hist[stds[t] >> 16], 1u);
}
__global__ __launch_bounds__(256) void k4a() {
    __shared__ unsigned part[256];
    unsigned s = 0;
    for (int i = 0; i < 256; i++) s += g_hist[threadIdx.x * 256 + i];
    part[threadIdx.x] = s;
    __syncthreads();
    if (threadIdx.x == 0) {
        unsigned cum = 0; int seg = 0;
        for (; seg < 256; seg++) { if (cum + part[seg] >= 64) break; cum += part[seg]; }
        unsigned B = 65535u;
        if (seg < 256)
            for (int i = seg * 256; i < seg * 256 + 256; i++) {
                if (cum + g_hist[i] >= 64) { B = (unsigned)i; break; }
                cum += g_hist[i];
            }
        g_misc[1] = B; g_misc[2] = cum;
    }
}
__global__ void k3b(const unsigned* __restrict__ stds) {
    int t = blockIdx.x * blockDim.x + threadIdx.x;
    if (t >= NTILES) return;
    unsigned b = stds[t];
    if ((b >> 16) == g_misc[1]) atomicAdd(&g_hist2[b & 0xffffu], 1u);
}
__global__ __launch_bounds__(256) void k4b() {
    __shared__ unsigned part[256];
    unsigned s = 0;
    for (int i = 0; i < 256; i++) s += g_hist2[threadIdx.x * 256 + i];
    part[threadIdx.x] = s;
    __syncthreads();
    if (threadIdx.x == 0) {
        unsigned cum = g_misc[2]; int seg = 0;
        for (; seg < 256; seg++) { if (cum + part[seg] >= 64) break; cum += part[seg]; }
        unsigned S = 65535u;
        if (seg < 256)
            for (int i = seg * 256; i < seg * 256 + 256; i++) {
                if (cum + g_hist2[i] >= 64) { S = (unsigned)i; break; }
                cum += g_hist2[i];
            }
        g_misc[3] = S;
    }
}
__global__ void k5(const unsigned* __restrict__ stds) {
    int t = blockIdx.x * blockDim.x + threadIdx.x;
    if (t >= NTILES) return;
    unsigned b = stds[t];
    unsigned top = b >> 16, B = g_misc[1], S = g_misc[3];
    if (top < B || (top == B && (b & 0xffffu) <= S)) {
        unsigned pos = atomicAdd(&g_misc[0], 1u);
        if (pos < CAP) g_cand[pos] = ((unsigned long long)b << 32) | (unsigned)t;
    }
}
__global__ __launch_bounds__(256) void k6(int* __restrict__ sel) {
    __shared__ unsigned long long c[CAP];
    unsigned cnt = g_misc[0];
    int n = (cnt < CAP) ? (int)cnt : CAP;
    for (int i = threadIdx.x; i < n; i += 256) c[i] = g_cand[i];
    __syncthreads();
    for (int i = threadIdx.x; i < n; i += 256) {
        unsigned long long ki = c[i];
        int rank = 0;
        for (int jj = 0; jj < n; jj++) rank += (c[jj] < ki);
        if (rank < 64) sel[rank] = (int)(ki & 0xffffffffu);
    }
}

// ---------------------------------------------------------------------------
// Fold: all 64 slots from the verified ranking
// ---------------------------------------------------------------------------
__global__ __launch_bounds__(256) void k7(const float* __restrict__ in, float* __restrict__ out) {
    int k = blockIdx.x, ch = blockIdx.y;
    int t = g_sel[k];
    int h = (t / NT) * 8, w = (t % NT) * 8;
    const float* src = in + (size_t)ch * HW + (size_t)h * WIMG + w;
    float* dst = out + (size_t)ch * (512 * 512) + (size_t)(k >> 3) * 64 * 512 + (k & 7) * 64;
    for (int e = threadIdx.x; e < 4096; e += 256) {
        int r = e >> 6, cc = e & 63;
        dst[(size_t)r * 512 + cc] = src[(size_t)r * WIMG + cc];
    }
}

// ---------------------------------------------------------------------------
extern "C" void kernel_launch(void* const* d_in, const int* in_sizes, int n_in,
                              void* d_out, int out_size) {
    const float* in = (const float*)d_in[0];
    float* out = (float*)d_out;

    unsigned *stds, *hist, *hist2, *misc;
    int* sel;
    cudaGetSymbolAddress((void**)&stds, g_stds);
    cudaGetSymbolAddress((void**)&hist, g_hist);
    cudaGetSymbolAddress((void**)&hist2, g_hist2);
    cudaGetSymbolAddress((void**)&misc, g_misc);
    cudaGetSymbolAddress((void**)&sel, g_sel);

    auto blocks = [](long n) { return (unsigned)((n + 255) / 256); };

    cudaMemsetAsync(hist, 0, 65536 * sizeof(unsigned));
    cudaMemsetAsync(hist2, 0, 65536 * sizeof(unsigned));
    cudaMemsetAsync(misc, 0, 4 * sizeof(unsigned));

    K1<<<dim3(blocks(NC), NB), 256>>>(in);
    K2a<<<blocks(2L * 16 * NC), 256>>>();
    K2b<<<blocks(2L * NC), 256>>>();
    K2c<<<blocks(2L * (NB - 16) * NC), 256>>>();
    K3<<<blocks(2L * NR * NC), 256>>>();
    K4<<<blocks(2L * NR * NB), 256>>>();
    K5a<<<blocks(2L * NR * 16), 256>>>();
    K5b<<<blocks(2L * NR), 256>>>();
    K5c<<<blocks(2L * NR * (NB - 16)), 256>>>();
    K6<<<blocks(2L * NR * NR), 256>>>();

    kStd<<<blocks(NTILES), 256>>>(stds);
    k3h<<<blocks(NTILES), 256>>>(stds);
    k4a<<<1, 256>>>();
    k3b<<<blocks(NTILES), 256>>>(stds);
    k4b<<<1, 256>>>();
    k5<<<blocks(NTILES), 256>>>(stds);
    k6<<<1, 256>>>(sel);

    k7<<<dim3(64, 3), 256>>>(in, out);
}